// round 13
// baseline (speedup 1.0000x reference)
#include <cuda_runtime.h>
#include <cstdint>

// Problem constants (fixed by the dataset)
#define KMAX      24     // max n-grams per word
#define ROW_BYTES 512    // E=128 fp32
#define VMAX      32768  // >= vocab size (32000)

// Zero row: padded slot ids are 0 and must contribute zero (reference zeroes
// table row 0; raw input row 0 is NOT zero). Static .bss device global.
__device__ __align__(256) float g_zero_row[128];

// Dedup state: claim flag + representative output position per vocab word.
// g_claim starts zero (.bss) and is RESET to zero by the tail of copy_kernel
// each launch -> every launch sees identical state (deterministic).
__device__ int g_claim[VMAX];
__device__ int g_rep[VMAX];

// 256-bit table gather, L2 evict_last (keep the 102MB table L2-resident).
__device__ __forceinline__ void ldg256_evl(const void* p, uint64_t d[4]) {
    asm("ld.global.nc.L2::evict_last.v4.b64 {%0,%1,%2,%3}, [%4];"
        : "=l"(d[0]), "=l"(d[1]), "=l"(d[2]), "=l"(d[3])
        : "l"(p));
}

// Plain 256-bit load (copy-pass reads of freshly-written out rows).
__device__ __forceinline__ void ldg256(const void* p, uint64_t d[4]) {
    asm("ld.global.nc.v4.b64 {%0,%1,%2,%3}, [%4];"
        : "=l"(d[0]), "=l"(d[1]), "=l"(d[2]), "=l"(d[3])
        : "l"(p));
}

// Plain 256-bit store (representative rows: re-read by the copy pass).
__device__ __forceinline__ void stg256(void* p, const uint64_t d[4]) {
    asm volatile("st.global.v4.b64 [%0], {%1,%2,%3,%4};"
                 :: "l"(p), "l"(d[0]), "l"(d[1]), "l"(d[2]), "l"(d[3])
                 : "memory");
}

// 256-bit store, L2 evict_first (duplicate rows: never re-read).
__device__ __forceinline__ void stg256_evf(void* p, const uint64_t d[4]) {
    asm volatile("st.global.L2::evict_first.v4.b64 [%0], {%1,%2,%3,%4};"
                 :: "l"(p), "l"(d[0]), "l"(d[1]), "l"(d[2]), "l"(d[3])
                 : "memory");
}

// ---------------------------------------------------------------- kernel 1
// One warp per batch position. First warp to claim a word gathers its mean
// embedding (two ngram rows per LDG.256; warp-uniform trip ceil(cnt/2)) and
// writes it DIRECTLY to out[pos], recording rep[word]=pos. Duplicate-word
// warps exit. ids/cnt are loaded speculatively BEFORE the claim resolves so
// the ~300cyc atomic latency overlaps the id fetch.
__global__ __launch_bounds__(256, 6)
void compute_kernel(const int* __restrict__ word_idx,
                    const int* __restrict__ ngram_ids,
                    const int* __restrict__ ngram_counts,
                    const char* __restrict__ emb,    // byte view of table
                    char* __restrict__ out,          // byte view of output
                    int n_words) {
    const int pos  = (blockIdx.x * blockDim.x + threadIdx.x) >> 5;
    const int lane = threadIdx.x & 31;
    if (pos >= n_words) return;

    const int w = __ldg(&word_idx[pos]);

    // Claim + speculative prologue loads, all in flight together.
    int old = 0;
    if (lane == 0) old = atomicExch(&g_claim[w], 1);
    int id_l = 0;
    if (lane < KMAX) id_l = __ldg(&ngram_ids[w * KMAX + lane]);
    const int cnt = __ldg(&ngram_counts[w]);

    old = __shfl_sync(0xffffffffu, old, 0);
    if (old) return;                       // another warp owns this word
    if (lane == 0) g_rep[w] = pos;

    const int half = lane >> 4;       // 0: even slots, 1: odd slots
    const int sub  = lane & 15;       // 32B chunk within the 512B row
    const int pairs = (cnt + 1) >> 1; // warp-uniform trip count

    const char* zrow = (const char*)g_zero_row + sub * 32;

    float acc[8];
    #pragma unroll
    for (int i = 0; i < 8; ++i) acc[i] = 0.f;

    #pragma unroll
    for (int t = 0; t < KMAX / 2; ++t) {
        if (t >= pairs) break;          // warp-uniform: no divergence
        const int id = __shfl_sync(0xffffffffu, id_l, 2 * t + half);
        const void* p = id ? (const void*)(emb + (size_t)id * ROW_BYTES + sub * 32)
                           : (const void*)zrow;   // padded slot -> zero row
        uint64_t d[4];
        ldg256_evl(p, d);
        #pragma unroll
        for (int i = 0; i < 4; ++i) {
            acc[2 * i + 0] += __uint_as_float((uint32_t)d[i]);
            acc[2 * i + 1] += __uint_as_float((uint32_t)(d[i] >> 32));
        }
    }

    #pragma unroll
    for (int i = 0; i < 8; ++i)
        acc[i] += __shfl_xor_sync(0xffffffffu, acc[i], 16);

    const float inv = 1.0f / (float)cnt;
    if (half == 0) {
        uint64_t q[4];
        #pragma unroll
        for (int i = 0; i < 4; ++i) {
            const uint32_t lo = __float_as_uint(acc[2 * i + 0] * inv);
            const uint32_t hi = __float_as_uint(acc[2 * i + 1] * inv);
            q[i] = (uint64_t)lo | ((uint64_t)hi << 32);
        }
        stg256(out + (size_t)pos * ROW_BYTES + sub * 32, q);
    }
}

// ---------------------------------------------------------------- kernel 2
// Fill duplicate positions, ONE WARP PER POSITION: the word_idx and rep
// loads are warp-broadcast (one transaction each), the r==pos test is
// warp-uniform, and the 512B copy is 16 parallel 32B lanes -> the dependent
// chain is paid once per warp instead of once per 32B chunk.
// Also resets g_claim for the next replay (replaces a clear kernel).
__global__ __launch_bounds__(256)
void copy_kernel(const int* __restrict__ word_idx,
                 char* __restrict__ out,            // byte view of output
                 int n_words) {
    const int gtid = blockIdx.x * blockDim.x + threadIdx.x;
    if (gtid < VMAX) g_claim[gtid] = 0;    // reset for next replay

    const int pos  = gtid >> 5;
    const int lane = gtid & 31;
    if (pos >= n_words) return;

    const int w = __ldg(&word_idx[pos]);   // warp-broadcast
    const int r = __ldg(&g_rep[w]);        // warp-broadcast, L2-hot
    if (r == pos) return;                  // representative: already written

    if (lane < 16) {                       // 16 lanes x 32B = 512B row
        uint64_t d[4];
        ldg256(out + (size_t)r * ROW_BYTES + lane * 32, d);
        stg256_evf(out + (size_t)pos * ROW_BYTES + lane * 32, d);
    }
}

extern "C" void kernel_launch(void* const* d_in, const int* in_sizes, int n_in,
                              void* d_out, int out_size) {
    const int*   word_idx     = (const int*)d_in[0];   // [B*S]
    const int*   ngram_ids    = (const int*)d_in[1];   // [V*24]
    const int*   ngram_counts = (const int*)d_in[2];   // [V]
    const char*  emb_table    = (const char*)d_in[3];  // [NG*128] f32
    char*        outp         = (char*)d_out;

    const int n_words = in_sizes[0];                   // 32768

    compute_kernel<<<(n_words * 32 + 255) / 256, 256>>>(word_idx, ngram_ids,
                                                        ngram_counts,
                                                        emb_table, outp,
                                                        n_words);
    copy_kernel<<<(n_words * 32 + 255) / 256, 256>>>(word_idx, outp, n_words);
}

// round 14
// speedup vs baseline: 1.1631x; 1.1631x over previous
#include <cuda_runtime.h>
#include <cstdint>

// Problem constants (fixed by the dataset)
#define KMAX      24    // max n-grams per word
#define ROW_BYTES 512   // E=128 fp32

// Zero row for the odd trailing slot when cnt is odd (padded id 0 -> zero
// contribution; raw table row 0 is NOT zero, reference zeroes it).
__device__ __align__(256) float g_zero_row[128];

// 256-bit table gather, L2 evict_last (keep the 102MB table resident in the
// 126MB L2 across graph replays; output stream is evict_first below).
__device__ __forceinline__ void ldg256_evl(const void* p, uint64_t d[4]) {
    asm("ld.global.nc.L2::evict_last.v4.b64 {%0,%1,%2,%3}, [%4];"
        : "=l"(d[0]), "=l"(d[1]), "=l"(d[2]), "=l"(d[3])
        : "l"(p));
}

// 256-bit output store, L2 evict_first (pure 16.8MB stream, never re-read).
__device__ __forceinline__ void stg256_evf(void* p, const uint64_t d[4]) {
    asm volatile("st.global.L2::evict_first.v4.b64 [%0], {%1,%2,%3,%4};"
                 :: "l"(p), "l"(d[0]), "l"(d[1]), "l"(d[2]), "l"(d[3])
                 : "memory");
}

// word_idx:      [B*S]      int32
// ngram_ids:     [V, 24]    int32   (slot >= count padded with 0)
// ngram_counts:  [V]        int32
// emb_table:     [NG, 128]  float32
// out:           [B*S, 128] float32 = mean over valid ngram embeddings
//
// One warp per word. Each LDG.256 fetches TWO ngram rows (lanes 0-15 even
// slot, 16-31 odd). Warp-uniform trip count ceil(cnt/2).
// 64-thread blocks: SMs backfill at block granularity, and block retirement
// waits on its slowest warp — E[max of 2 warps' trips] ~ 5.9 vs E[max of 8]
// ~ 10.4, so small blocks cut the count-imbalance inflation.
__global__ __launch_bounds__(64)
void ngram_emb_kernel(const int* __restrict__ word_idx,
                      const int* __restrict__ ngram_ids,
                      const int* __restrict__ ngram_counts,
                      const char* __restrict__ emb,    // byte view of table
                      char* __restrict__ out,          // byte view of output
                      int n_words) {
    const int warp = (blockIdx.x * blockDim.x + threadIdx.x) >> 5;
    const int lane = threadIdx.x & 31;
    if (warp >= n_words) return;

    const int half = lane >> 4;       // 0: even slots, 1: odd slots
    const int sub  = lane & 15;       // 32B chunk within the 512B row

    const int w = __ldg(&word_idx[warp]);

    // Lanes 0..23 fetch the 24 ngram ids for this word (coalesced 96B read).
    int id_l = 0;
    if (lane < KMAX) id_l = __ldg(&ngram_ids[w * KMAX + lane]);
    const int cnt = __ldg(&ngram_counts[w]);
    const int pairs = (cnt + 1) >> 1;   // warp-uniform trip count

    const char* zrow = (const char*)g_zero_row + sub * 32;

    float acc[8];
    #pragma unroll
    for (int i = 0; i < 8; ++i) acc[i] = 0.f;

    #pragma unroll
    for (int t = 0; t < KMAX / 2; ++t) {
        if (t >= pairs) break;          // warp-uniform: no divergence
        const int id = __shfl_sync(0xffffffffu, id_l, 2 * t + half);
        // Only the odd trailing slot (cnt odd) has id==0 here -> zero row.
        const void* p = id ? (const void*)(emb + (size_t)id * ROW_BYTES + sub * 32)
                           : (const void*)zrow;
        uint64_t d[4];
        ldg256_evl(p, d);
        #pragma unroll
        for (int i = 0; i < 4; ++i) {
            acc[2 * i + 0] += __uint_as_float((uint32_t)d[i]);
            acc[2 * i + 1] += __uint_as_float((uint32_t)(d[i] >> 32));
        }
    }

    // Combine even-slot half and odd-slot half.
    #pragma unroll
    for (int i = 0; i < 8; ++i)
        acc[i] += __shfl_xor_sync(0xffffffffu, acc[i], 16);

    const float inv = 1.0f / (float)cnt;
    if (half == 0) {
        uint64_t q[4];
        #pragma unroll
        for (int i = 0; i < 4; ++i) {
            const uint32_t lo = __float_as_uint(acc[2 * i + 0] * inv);
            const uint32_t hi = __float_as_uint(acc[2 * i + 1] * inv);
            q[i] = (uint64_t)lo | ((uint64_t)hi << 32);
        }
        stg256_evf(out + (size_t)warp * ROW_BYTES + sub * 32, q);
    }
}

extern "C" void kernel_launch(void* const* d_in, const int* in_sizes, int n_in,
                              void* d_out, int out_size) {
    const int*   word_idx     = (const int*)d_in[0];   // [B*S]
    const int*   ngram_ids    = (const int*)d_in[1];   // [V*24]
    const int*   ngram_counts = (const int*)d_in[2];   // [V]
    const char*  emb_table    = (const char*)d_in[3];  // [NG*128] f32
    char*        outp         = (char*)d_out;

    const int n_words = in_sizes[0];                   // 32768
    const int threads = 64;                            // 2 warps / block
    const int warps_per_block = threads / 32;
    const int blocks = (n_words + warps_per_block - 1) / warps_per_block;

    ngram_emb_kernel<<<blocks, threads>>>(word_idx, ngram_ids, ngram_counts,
                                          emb_table, outp, n_words);
}

// round 15
// speedup vs baseline: 1.1735x; 1.0089x over previous
#include <cuda_runtime.h>
#include <cstdint>

// Problem constants (fixed by the dataset)
#define KMAX      24    // max n-grams per word
#define ROW_BYTES 512   // E=128 fp32

// Zero row for the odd trailing slot when cnt is odd (padded id 0 -> zero
// contribution; raw table row 0 is NOT zero, reference zeroes it).
__device__ __align__(256) float g_zero_row[128];

// 256-bit table gather, L2 evict_last (keep the 102MB table resident in the
// 126MB L2 across graph replays; output stream is evict_first below).
__device__ __forceinline__ void ldg256_evl(const void* p, uint64_t d[4]) {
    asm("ld.global.nc.L2::evict_last.v4.b64 {%0,%1,%2,%3}, [%4];"
        : "=l"(d[0]), "=l"(d[1]), "=l"(d[2]), "=l"(d[3])
        : "l"(p));
}

// 256-bit output store, L2 evict_first (pure 16.8MB stream, never re-read).
__device__ __forceinline__ void stg256_evf(void* p, const uint64_t d[4]) {
    asm volatile("st.global.L2::evict_first.v4.b64 [%0], {%1,%2,%3,%4};"
                 :: "l"(p), "l"(d[0]), "l"(d[1]), "l"(d[2]), "l"(d[3])
                 : "memory");
}

// word_idx:      [B*S]      int32
// ngram_ids:     [V, 24]    int32   (slot >= count padded with 0)
// ngram_counts:  [V]        int32
// emb_table:     [NG, 128]  float32
// out:           [B*S, 128] float32 = mean over valid ngram embeddings
//
// TWO words per warp, processed sequentially, with BOTH prologues (ids+cnt)
// issued up front: word B's prologue latency hides behind word A's gathers.
// Gather body: each LDG.256 fetches two ngram rows (lanes 0-15 even slot,
// 16-31 odd slot); warp-uniform trip count ceil(cnt/2).
__global__ __launch_bounds__(256)
void ngram_emb_kernel(const int* __restrict__ word_idx,
                      const int* __restrict__ ngram_ids,
                      const int* __restrict__ ngram_counts,
                      const char* __restrict__ emb,    // byte view of table
                      char* __restrict__ out,          // byte view of output
                      int n_words) {
    const int warp = (blockIdx.x * blockDim.x + threadIdx.x) >> 5;
    const int lane = threadIdx.x & 31;

    const int posA = warp * 2;
    const int posB = posA + 1;
    if (posA >= n_words) return;
    const bool hasB = (posB < n_words);

    const int half = lane >> 4;       // 0: even slots, 1: odd slots
    const int sub  = lane & 15;       // 32B chunk within the 512B row
    const char* zrow = (const char*)g_zero_row + sub * 32;

    // ---- both prologues in flight together -----------------------------
    const int wA = __ldg(&word_idx[posA]);
    const int wB = hasB ? __ldg(&word_idx[posB]) : wA;

    int idA = 0, idB = 0;
    if (lane < KMAX) {
        idA = __ldg(&ngram_ids[wA * KMAX + lane]);
        idB = __ldg(&ngram_ids[wB * KMAX + lane]);
    }
    const int cntA = __ldg(&ngram_counts[wA]);
    const int cntB = __ldg(&ngram_counts[wB]);
    const int pairsA = (cntA + 1) >> 1;   // warp-uniform trip counts
    const int pairsB = (cntB + 1) >> 1;

    // ---- word A ---------------------------------------------------------
    float acc[8];
    #pragma unroll
    for (int i = 0; i < 8; ++i) acc[i] = 0.f;

    #pragma unroll
    for (int t = 0; t < KMAX / 2; ++t) {
        if (t >= pairsA) break;         // warp-uniform: no divergence
        const int id = __shfl_sync(0xffffffffu, idA, 2 * t + half);
        const void* p = id ? (const void*)(emb + (size_t)id * ROW_BYTES + sub * 32)
                           : (const void*)zrow;
        uint64_t d[4];
        ldg256_evl(p, d);
        #pragma unroll
        for (int i = 0; i < 4; ++i) {
            acc[2 * i + 0] += __uint_as_float((uint32_t)d[i]);
            acc[2 * i + 1] += __uint_as_float((uint32_t)(d[i] >> 32));
        }
    }

    #pragma unroll
    for (int i = 0; i < 8; ++i)
        acc[i] += __shfl_xor_sync(0xffffffffu, acc[i], 16);

    {
        const float inv = 1.0f / (float)cntA;
        if (half == 0) {
            uint64_t q[4];
            #pragma unroll
            for (int i = 0; i < 4; ++i) {
                const uint32_t lo = __float_as_uint(acc[2 * i + 0] * inv);
                const uint32_t hi = __float_as_uint(acc[2 * i + 1] * inv);
                q[i] = (uint64_t)lo | ((uint64_t)hi << 32);
            }
            stg256_evf(out + (size_t)posA * ROW_BYTES + sub * 32, q);
        }
    }

    // ---- word B ---------------------------------------------------------
    if (!hasB) return;

    #pragma unroll
    for (int i = 0; i < 8; ++i) acc[i] = 0.f;

    #pragma unroll
    for (int t = 0; t < KMAX / 2; ++t) {
        if (t >= pairsB) break;         // warp-uniform: no divergence
        const int id = __shfl_sync(0xffffffffu, idB, 2 * t + half);
        const void* p = id ? (const void*)(emb + (size_t)id * ROW_BYTES + sub * 32)
                           : (const void*)zrow;
        uint64_t d[4];
        ldg256_evl(p, d);
        #pragma unroll
        for (int i = 0; i < 4; ++i) {
            acc[2 * i + 0] += __uint_as_float((uint32_t)d[i]);
            acc[2 * i + 1] += __uint_as_float((uint32_t)(d[i] >> 32));
        }
    }

    #pragma unroll
    for (int i = 0; i < 8; ++i)
        acc[i] += __shfl_xor_sync(0xffffffffu, acc[i], 16);

    {
        const float inv = 1.0f / (float)cntB;
        if (half == 0) {
            uint64_t q[4];
            #pragma unroll
            for (int i = 0; i < 4; ++i) {
                const uint32_t lo = __float_as_uint(acc[2 * i + 0] * inv);
                const uint32_t hi = __float_as_uint(acc[2 * i + 1] * inv);
                q[i] = (uint64_t)lo | ((uint64_t)hi << 32);
            }
            stg256_evf(out + (size_t)posB * ROW_BYTES + sub * 32, q);
        }
    }
}

extern "C" void kernel_launch(void* const* d_in, const int* in_sizes, int n_in,
                              void* d_out, int out_size) {
    const int*   word_idx     = (const int*)d_in[0];   // [B*S]
    const int*   ngram_ids    = (const int*)d_in[1];   // [V*24]
    const int*   ngram_counts = (const int*)d_in[2];   // [V]
    const char*  emb_table    = (const char*)d_in[3];  // [NG*128] f32
    char*        outp         = (char*)d_out;

    const int n_words = in_sizes[0];                   // 32768
    const int n_warps = (n_words + 1) / 2;             // 2 words per warp
    const int threads = 256;                           // 8 warps / block
    const int warps_per_block = threads / 32;
    const int blocks = (n_warps + warps_per_block - 1) / warps_per_block;

    ngram_emb_kernel<<<blocks, threads>>>(word_idx, ngram_ids, ngram_counts,
                                          emb_table, outp, n_words);
}